// round 5
// baseline (speedup 1.0000x reference)
#include <cuda_runtime.h>
#include <cuda_bf16.h>
#include <cstdint>

// Problem constants (fixed shapes)
#define B_SZ   256
#define T_SZ   512
#define EMB    128
#define HID    256
#define NCLS   32000

// Scratch: h0 at last timestep, stored bf16 for tensor-core GEMM
__device__ __nv_bfloat16 g_h0[B_SZ * HID];

// ---------------------------------------------------------------------------
// Kernel 1: h0_last[b, h] for the 256 last-timestep tokens. (R4, validated)
// Grid (4, 32): x = hidden split (64 cols), y = batch group (8 rows).
// ---------------------------------------------------------------------------
__global__ void __launch_bounds__(256) lstm_h0_kernel(
    const int* __restrict__ X, const float* __restrict__ C_table,
    const float* __restrict__ U_i, const float* __restrict__ b_i,
    const float* __restrict__ U_c, const float* __restrict__ b_c,
    const float* __restrict__ U_o, const float* __restrict__ b_o)
{
    __shared__ float E_s[8][EMB];
    const int tid = threadIdx.x;
    const int b0  = blockIdx.y * 8;

    for (int i = tid; i < 8 * EMB; i += 256) {
        int b = i >> 7;
        int e = i & (EMB - 1);
        int tok = X[(b0 + b) * T_SZ + (T_SZ - 1)];
        E_s[b][e] = C_table[tok * EMB + e];
    }
    __syncthreads();

    const int h    = blockIdx.x * 64 + (tid & 63);
    const int bsub = tid >> 6;
    const int r0   = bsub * 2;

    float ai[2], ag[2], ao[2];
    const float bi = b_i[h], bc = b_c[h], bo = b_o[h];
#pragma unroll
    for (int r = 0; r < 2; r++) { ai[r] = bi; ag[r] = bc; ao[r] = bo; }

#pragma unroll 4
    for (int e = 0; e < EMB; e++) {
        float ui = U_i[e * HID + h];
        float uc = U_c[e * HID + h];
        float uo = U_o[e * HID + h];
#pragma unroll
        for (int r = 0; r < 2; r++) {
            float ev = E_s[r0 + r][e];
            ai[r] = fmaf(ev, ui, ai[r]);
            ag[r] = fmaf(ev, uc, ag[r]);
            ao[r] = fmaf(ev, uo, ao[r]);
        }
    }

#pragma unroll
    for (int r = 0; r < 2; r++) {
        float i0 = 1.0f / (1.0f + __expf(-ai[r]));
        float g0 = tanhf(ag[r]);
        float o0 = 1.0f / (1.0f + __expf(-ao[r]));
        float c0 = i0 * g0;
        float h0 = o0 * tanhf(c0);
        g_h0[(b0 + r0 + r) * HID + h] = __float2bfloat16(h0);
    }
}

// ---------------------------------------------------------------------------
// Kernel 2: logits[256, 32000] = h0[256,256] @ W_w[32000,256]^T + b_out
// Monolithic (load-all -> one sync -> compute) bf16 mma.sync GEMM.
// NO cp.async. Overlap comes from 2 CTAs/SM.
//   CTA tile: M=128 x N=64, K=256. grid = (500, 2) = 1000 CTAs, 256 threads.
//   A_s [128][264] bf16 (g_h0 slice); B_s [64][264] bf16 (W converted at load).
//   Compute: 16 kk steps, per warp per kk: 4 ldmatrix.x4 (A) + 1 ldmatrix.x4
//   (B, covers both n8 tiles of the warp's 16-wide slice) + 8 MMA.
//   Stride 264 (528B): 8-row LDSM phases hit distinct 16B bank groups.
// ---------------------------------------------------------------------------
#define BM      128
#define BN      64
#define ASTR    264              // row stride in bf16 (528B)

__global__ void __launch_bounds__(256, 2) logits_kernel(
    const float* __restrict__ W_w, const float* __restrict__ b_out,
    float* __restrict__ out)
{
    extern __shared__ char smem_raw[];
    __nv_bfloat16* A_s = (__nv_bfloat16*)smem_raw;              // [128][ASTR]
    __nv_bfloat16* B_s = (__nv_bfloat16*)(smem_raw + BM * ASTR * 2); // [64][ASTR]

    const int tid = threadIdx.x;
    const int n0  = blockIdx.x * BN;
    const int m0  = blockIdx.y * BM;

    // --- load A: g_h0 rows [m0, m0+128), 128 x 32 16B-segs, LDG.128 -> STS.128
    {
        const uint4* src = (const uint4*)(g_h0 + (size_t)m0 * HID);
#pragma unroll
        for (int k = 0; k < 16; k++) {
            int idx = tid + k * 256;       // 4096 segs
            int row = idx >> 5;
            int seg = idx & 31;
            uint4 v = src[row * 32 + seg];
            *(uint4*)((char*)A_s + row * (ASTR * 2) + seg * 16) = v;
        }
    }
    // --- load B: W rows [n0, n0+64) fp32 -> bf16, 64 x 32 segs of 8 bf16 each
    {
#pragma unroll
        for (int k = 0; k < 8; k++) {
            int idx = tid + k * 256;       // 2048 segs
            int row = idx >> 5;
            int seg = idx & 31;            // 8 bf16 = 8 fp32 = 2 float4
            const float4* src =
                (const float4*)(W_w + (size_t)(n0 + row) * HID + seg * 8);
            float4 f0 = src[0];
            float4 f1 = src[1];
            __nv_bfloat162 p0 = __floats2bfloat162_rn(f0.x, f0.y);
            __nv_bfloat162 p1 = __floats2bfloat162_rn(f0.z, f0.w);
            __nv_bfloat162 p2 = __floats2bfloat162_rn(f1.x, f1.y);
            __nv_bfloat162 p3 = __floats2bfloat162_rn(f1.z, f1.w);
            uint4 v;
            v.x = *(uint32_t*)&p0; v.y = *(uint32_t*)&p1;
            v.z = *(uint32_t*)&p2; v.w = *(uint32_t*)&p3;
            *(uint4*)((char*)B_s + row * (ASTR * 2) + seg * 16) = v;
        }
    }
    __syncthreads();

    const int wid  = tid >> 5;
    const int lane = tid & 31;
    const int wm   = wid >> 2;      // 0..1 -> M offset wm*64
    const int wn   = wid & 3;       // 0..3 -> N offset wn*16
    const int gr   = lane >> 2;
    const int tig  = lane & 3;
    // A ldmatrix lane address (validated in R4):
    const int lm_row = (lane & 15);
    const int lm_col = ((lane >> 4) & 1) << 3;
    // B ldmatrix lane address: tiles = (n0-7,k0-7),(n0-7,k8-15),(n8-15,k0-7),(n8-15,k8-15)
    const int bl_row = ((lane >> 4) << 3) + (lane & 7);   // n row within 16
    const int bl_col = ((lane >> 3) & 1) << 3;            // k half

    float acc[4][2][4];
#pragma unroll
    for (int mi = 0; mi < 4; mi++)
#pragma unroll
        for (int ni = 0; ni < 2; ni++)
#pragma unroll
            for (int r = 0; r < 4; r++) acc[mi][ni][r] = 0.0f;

#pragma unroll
    for (int kk = 0; kk < HID / 16; kk++) {
        const int kb = kk * 16;
        uint32_t a[4][4];
#pragma unroll
        for (int mi = 0; mi < 4; mi++) {
            uint32_t addr = (uint32_t)__cvta_generic_to_shared(
                &A_s[(wm * 64 + mi * 16 + lm_row) * ASTR + kb + lm_col]);
            asm volatile(
                "ldmatrix.sync.aligned.m8n8.x4.shared.b16 {%0,%1,%2,%3}, [%4];"
                : "=r"(a[mi][0]), "=r"(a[mi][1]), "=r"(a[mi][2]), "=r"(a[mi][3])
                : "r"(addr));
        }
        uint32_t bf[4];   // bf[0],bf[1] = ni0 {b0,b1}; bf[2],bf[3] = ni1 {b0,b1}
        {
            uint32_t addr = (uint32_t)__cvta_generic_to_shared(
                &B_s[(wn * 16 + bl_row) * ASTR + kb + bl_col]);
            asm volatile(
                "ldmatrix.sync.aligned.m8n8.x4.shared.b16 {%0,%1,%2,%3}, [%4];"
                : "=r"(bf[0]), "=r"(bf[1]), "=r"(bf[2]), "=r"(bf[3])
                : "r"(addr));
        }
#pragma unroll
        for (int mi = 0; mi < 4; mi++) {
#pragma unroll
            for (int ni = 0; ni < 2; ni++) {
                asm volatile(
                    "mma.sync.aligned.m16n8k16.row.col.f32.bf16.bf16.f32 "
                    "{%0,%1,%2,%3}, {%4,%5,%6,%7}, {%8,%9}, {%0,%1,%2,%3};"
                    : "+f"(acc[mi][ni][0]), "+f"(acc[mi][ni][1]),
                      "+f"(acc[mi][ni][2]), "+f"(acc[mi][ni][3])
                    : "r"(a[mi][0]), "r"(a[mi][1]), "r"(a[mi][2]), "r"(a[mi][3]),
                      "r"(bf[ni * 2]), "r"(bf[ni * 2 + 1]));
            }
        }
    }

    // ---- epilogue: add b_out, fp32 float2 stores ----
    float bo0[2], bo1[2];
#pragma unroll
    for (int ni = 0; ni < 2; ni++) {
        int col = n0 + wn * 16 + ni * 8 + tig * 2;
        bo0[ni] = b_out[col];
        bo1[ni] = b_out[col + 1];
    }
#pragma unroll
    for (int mi = 0; mi < 4; mi++) {
        int row = m0 + wm * 64 + mi * 16 + gr;
#pragma unroll
        for (int ni = 0; ni < 2; ni++) {
            int col = n0 + wn * 16 + ni * 8 + tig * 2;
            float2 v0 = make_float2(acc[mi][ni][0] + bo0[ni],
                                    acc[mi][ni][1] + bo1[ni]);
            float2 v1 = make_float2(acc[mi][ni][2] + bo0[ni],
                                    acc[mi][ni][3] + bo1[ni]);
            *(float2*)(&out[(size_t)row * NCLS + col])       = v0;
            *(float2*)(&out[(size_t)(row + 8) * NCLS + col]) = v1;
        }
    }
}

// ---------------------------------------------------------------------------
// Launcher
// Input order: 0=X 1=C_table 2=U_i 3=V_i 4=b_i 5=U_f 6=V_f 7=b_f
//  8=U_c 9=V_c 10=b_c 11=U_o 12=V_o 13=b_o 14..25=layer1 (unused) 26=W_w 27=b_out
// ---------------------------------------------------------------------------
extern "C" void kernel_launch(void* const* d_in, const int* in_sizes, int n_in,
                              void* d_out, int out_size)
{
    const int*   X       = (const int*)d_in[0];
    const float* C_table = (const float*)d_in[1];
    const float* U_i     = (const float*)d_in[2];
    const float* b_i     = (const float*)d_in[4];
    const float* U_c     = (const float*)d_in[8];
    const float* b_c     = (const float*)d_in[10];
    const float* U_o     = (const float*)d_in[11];
    const float* b_o     = (const float*)d_in[13];
    const float* W_w     = (const float*)d_in[26];
    const float* b_out   = (const float*)d_in[27];
    float* out = (float*)d_out;

    dim3 grid1(4, 32);
    lstm_h0_kernel<<<grid1, 256>>>(X, C_table, U_i, b_i, U_c, b_c, U_o, b_o);

    const int smem_bytes = (BM + BN) * ASTR * 2;   // 101376
    cudaFuncSetAttribute(logits_kernel,
                         cudaFuncAttributeMaxDynamicSharedMemorySize, smem_bytes);
    dim3 grid2(NCLS / BN, B_SZ / BM);   // (500, 2)
    logits_kernel<<<grid2, 256, smem_bytes>>>(W_w, b_out, out);
}

// round 6
// speedup vs baseline: 1.2709x; 1.2709x over previous
#include <cuda_runtime.h>
#include <cuda_bf16.h>
#include <cstdint>

// Problem constants (fixed shapes)
#define B_SZ   256
#define T_SZ   512
#define EMB    128
#define HID    256
#define NCLS   32000

// Scratch: h0 at last timestep, stored bf16 for tensor-core GEMM
__device__ __nv_bfloat16 g_h0[B_SZ * HID];

// ---------------------------------------------------------------------------
// Kernel 1: h0_last[b, h] for the 256 last-timestep tokens. (R4/R5, validated)
// ---------------------------------------------------------------------------
__global__ void __launch_bounds__(256) lstm_h0_kernel(
    const int* __restrict__ X, const float* __restrict__ C_table,
    const float* __restrict__ U_i, const float* __restrict__ b_i,
    const float* __restrict__ U_c, const float* __restrict__ b_c,
    const float* __restrict__ U_o, const float* __restrict__ b_o)
{
    __shared__ float E_s[8][EMB];
    const int tid = threadIdx.x;
    const int b0  = blockIdx.y * 8;

    for (int i = tid; i < 8 * EMB; i += 256) {
        int b = i >> 7;
        int e = i & (EMB - 1);
        int tok = X[(b0 + b) * T_SZ + (T_SZ - 1)];
        E_s[b][e] = C_table[tok * EMB + e];
    }
    __syncthreads();

    const int h    = blockIdx.x * 64 + (tid & 63);
    const int bsub = tid >> 6;
    const int r0   = bsub * 2;

    float ai[2], ag[2], ao[2];
    const float bi = b_i[h], bc = b_c[h], bo = b_o[h];
#pragma unroll
    for (int r = 0; r < 2; r++) { ai[r] = bi; ag[r] = bc; ao[r] = bo; }

#pragma unroll 4
    for (int e = 0; e < EMB; e++) {
        float ui = U_i[e * HID + h];
        float uc = U_c[e * HID + h];
        float uo = U_o[e * HID + h];
#pragma unroll
        for (int r = 0; r < 2; r++) {
            float ev = E_s[r0 + r][e];
            ai[r] = fmaf(ev, ui, ai[r]);
            ag[r] = fmaf(ev, uc, ag[r]);
            ao[r] = fmaf(ev, uo, ao[r]);
        }
    }

#pragma unroll
    for (int r = 0; r < 2; r++) {
        float i0 = 1.0f / (1.0f + __expf(-ai[r]));
        float g0 = tanhf(ag[r]);
        float o0 = 1.0f / (1.0f + __expf(-ao[r]));
        float c0 = i0 * g0;
        float h0 = o0 * tanhf(c0);
        g_h0[(b0 + r0 + r) * HID + h] = __float2bfloat16(h0);
    }
}

// ---------------------------------------------------------------------------
// Kernel 2: logits[256, 32000] = h0[256,256] @ W_w[32000,256]^T + b_out
// Deep-pipelined bf16 mma.sync GEMM.
//   CTA tile: M=256 (full batch!) x N=128, K=256. grid = (250,1), 512 threads.
//   B rows touched by exactly ONE CTA (minimal DRAM traffic).
//   A (h0, bf16) resident in smem; B streamed fp32 via cp.async in 8 K-chunks
//   of 32, FOUR buffers, constant wait_group 2 -> 3 chunks always in flight.
//   A fragments via ldmatrix.x4 (validated); B fragments LDS.64 BSTR=40
//   (validated conflict-free), fp32->bf16 at fragment-load time.
//   Smem: A 256*264*2 = 135168 + B 4*128*40*4 = 81920 -> 217088 B, 1 CTA/SM.
// ---------------------------------------------------------------------------
#define BM      256
#define BN      128
#define ASTR    264              // A_s row stride in bf16 (528B = 33*16)
#define CHUNK_K 32
#define NCHUNK  (HID / CHUNK_K)  // 8
#define NBUF    4
#define BSTR    40               // B_s row stride in fp32 (160B = 10*16)
#define BBUF    (BN * BSTR)      // one B buffer, floats (5120)

__device__ __forceinline__ void cp16(void* dst_smem, const void* src) {
    uint32_t d = (uint32_t)__cvta_generic_to_shared(dst_smem);
    asm volatile("cp.async.cg.shared.global [%0], [%1], 16;" :: "r"(d), "l"(src));
}
__device__ __forceinline__ void cp_commit() {
    asm volatile("cp.async.commit_group;" ::: "memory");
}
__device__ __forceinline__ void cp_wait2() {
    asm volatile("cp.async.wait_group 2;" ::: "memory");
}

// Issue one B chunk (CHUNK_K=32 fp32 cols of 128 rows) into buffer `dst`.
__device__ __forceinline__ void issue_b_chunk(
    float* dst, const float* __restrict__ W_w, int n0, int ck, int tid)
{
#pragma unroll
    for (int k = 0; k < 2; k++) {
        int idx = tid + k * 512;           // 1024 segs (128 rows x 8 segs)
        int row = idx >> 3;
        int seg = idx & 7;                 // 8 segs * 16B = 128B = 32 floats
        cp16(dst + row * BSTR + seg * 4,
             W_w + (size_t)(n0 + row) * HID + ck * CHUNK_K + seg * 4);
    }
}

__global__ void __launch_bounds__(512, 1) logits_kernel(
    const float* __restrict__ W_w, const float* __restrict__ b_out,
    float* __restrict__ out)
{
    extern __shared__ char smem_raw[];
    __nv_bfloat16* A_s = (__nv_bfloat16*)smem_raw;              // [256][ASTR]
    float*         B_s = (float*)(smem_raw + BM * ASTR * 2);    // 4*[128][BSTR]

    const int tid = threadIdx.x;
    const int n0  = blockIdx.x * BN;

    // --- issue A load: all of g_h0 (128KB) in 16B segments ---
    {
        const char* src = (const char*)g_h0;
#pragma unroll
        for (int k = 0; k < 16; k++) {
            int idx = tid + k * 512;       // 8192 segs (256 rows x 32 segs)
            int row = idx >> 5;
            int seg = idx & 31;
            cp16((char*)A_s + row * (ASTR * 2) + seg * 16,
                 src + row * (HID * 2) + seg * 16);
        }
    }
    issue_b_chunk(B_s + 0 * BBUF, W_w, n0, 0, tid);
    cp_commit();                               // group: A + chunk0
    issue_b_chunk(B_s + 1 * BBUF, W_w, n0, 1, tid);
    cp_commit();                               // group: chunk1
    issue_b_chunk(B_s + 2 * BBUF, W_w, n0, 2, tid);
    cp_commit();                               // group: chunk2

    const int wid  = tid >> 5;
    const int lane = tid & 31;
    const int wm   = wid >> 2;      // 0..3 -> M offset wm*64
    const int wn   = wid & 3;       // 0..3 -> N offset wn*32
    const int gr   = lane >> 2;
    const int tig  = lane & 3;
    // ldmatrix lane address components (validated R5):
    const int lm_row = (lane & 15);
    const int lm_col = ((lane >> 4) & 1) << 3;

    float acc[4][4][4];
#pragma unroll
    for (int mi = 0; mi < 4; mi++)
#pragma unroll
        for (int ni = 0; ni < 4; ni++)
#pragma unroll
            for (int r = 0; r < 4; r++) acc[mi][ni][r] = 0.0f;

#pragma unroll
    for (int c = 0; c < NCHUNK; c++) {
        cp_wait2();        // chunk c (and A on first iter) complete
        __syncthreads();   // make all threads' cp.async results visible

        // ---- compute 2 kk steps of chunk c from buf c&3 ----
        const float* Bb = B_s + (c & 3) * BBUF;
#pragma unroll
        for (int kkl = 0; kkl < CHUNK_K / 16; kkl++) {
            const int kbg = c * CHUNK_K + kkl * 16;   // global K offset (A)
            const int kbl = kkl * 16;                 // local K offset (B)
            uint32_t a[4][4];
#pragma unroll
            for (int mi = 0; mi < 4; mi++) {
                uint32_t addr = (uint32_t)__cvta_generic_to_shared(
                    &A_s[(wm * 64 + mi * 16 + lm_row) * ASTR + kbg + lm_col]);
                asm volatile(
                    "ldmatrix.sync.aligned.m8n8.x4.shared.b16 {%0,%1,%2,%3}, [%4];"
                    : "=r"(a[mi][0]), "=r"(a[mi][1]), "=r"(a[mi][2]), "=r"(a[mi][3])
                    : "r"(addr));
            }
            uint32_t bf[4][2];
#pragma unroll
            for (int ni = 0; ni < 4; ni++) {
                const float* p =
                    Bb + (wn * 32 + ni * 8 + gr) * BSTR + kbl + tig * 2;
                float2 f0 = *(const float2*)(p);
                float2 f1 = *(const float2*)(p + 8);
                __nv_bfloat162 p0 = __floats2bfloat162_rn(f0.x, f0.y);
                __nv_bfloat162 p1 = __floats2bfloat162_rn(f1.x, f1.y);
                bf[ni][0] = *(const uint32_t*)&p0;
                bf[ni][1] = *(const uint32_t*)&p1;
            }
#pragma unroll
            for (int mi = 0; mi < 4; mi++) {
#pragma unroll
                for (int ni = 0; ni < 4; ni++) {
                    asm volatile(
                        "mma.sync.aligned.m16n8k16.row.col.f32.bf16.bf16.f32 "
                        "{%0,%1,%2,%3}, {%4,%5,%6,%7}, {%8,%9}, {%0,%1,%2,%3};"
                        : "+f"(acc[mi][ni][0]), "+f"(acc[mi][ni][1]),
                          "+f"(acc[mi][ni][2]), "+f"(acc[mi][ni][3])
                        : "r"(a[mi][0]), "r"(a[mi][1]), "r"(a[mi][2]), "r"(a[mi][3]),
                          "r"(bf[ni][0]), "r"(bf[ni][1]));
                }
            }
        }
        __syncthreads();   // all reads of buf c&3 done before refilling below

        // ---- issue chunk c+3 into buf (c+3)&3 (buf of chunk c-1, now free) ----
        if (c + 3 < NCHUNK)
            issue_b_chunk(B_s + ((c + 3) & 3) * BBUF, W_w, n0, c + 3, tid);
        cp_commit();       // unconditional: keeps wait_group numbering exact
    }

    // ---- epilogue: add b_out, fp32 float2 stores ----
    float bo0[4], bo1[4];
#pragma unroll
    for (int ni = 0; ni < 4; ni++) {
        int col = n0 + wn * 32 + ni * 8 + tig * 2;
        bo0[ni] = b_out[col];
        bo1[ni] = b_out[col + 1];
    }
#pragma unroll
    for (int mi = 0; mi < 4; mi++) {
        int row = wm * 64 + mi * 16 + gr;
#pragma unroll
        for (int ni = 0; ni < 4; ni++) {
            int col = n0 + wn * 32 + ni * 8 + tig * 2;
            float2 v0 = make_float2(acc[mi][ni][0] + bo0[ni],
                                    acc[mi][ni][1] + bo1[ni]);
            float2 v1 = make_float2(acc[mi][ni][2] + bo0[ni],
                                    acc[mi][ni][3] + bo1[ni]);
            *(float2*)(&out[(size_t)row * NCLS + col])       = v0;
            *(float2*)(&out[(size_t)(row + 8) * NCLS + col]) = v1;
        }
    }
}

// ---------------------------------------------------------------------------
// Launcher
// Input order: 0=X 1=C_table 2=U_i 3=V_i 4=b_i 5=U_f 6=V_f 7=b_f
//  8=U_c 9=V_c 10=b_c 11=U_o 12=V_o 13=b_o 14..25=layer1 (unused) 26=W_w 27=b_out
// ---------------------------------------------------------------------------
extern "C" void kernel_launch(void* const* d_in, const int* in_sizes, int n_in,
                              void* d_out, int out_size)
{
    const int*   X       = (const int*)d_in[0];
    const float* C_table = (const float*)d_in[1];
    const float* U_i     = (const float*)d_in[2];
    const float* b_i     = (const float*)d_in[4];
    const float* U_c     = (const float*)d_in[8];
    const float* b_c     = (const float*)d_in[10];
    const float* U_o     = (const float*)d_in[11];
    const float* b_o     = (const float*)d_in[13];
    const float* W_w     = (const float*)d_in[26];
    const float* b_out   = (const float*)d_in[27];
    float* out = (float*)d_out;

    dim3 grid1(4, 32);
    lstm_h0_kernel<<<grid1, 256>>>(X, C_table, U_i, b_i, U_c, b_c, U_o, b_o);

    const int smem_bytes = BM * ASTR * 2 + NBUF * BBUF * (int)sizeof(float); // 217088
    cudaFuncSetAttribute(logits_kernel,
                         cudaFuncAttributeMaxDynamicSharedMemorySize, smem_bytes);
    logits_kernel<<<NCLS / BN, 512, smem_bytes>>>(W_w, b_out, out);
}